// round 3
// baseline (speedup 1.0000x reference)
#include <cuda_runtime.h>
#include <cuda_fp16.h>
#include <cuda.h>
#include <cstdint>

// ----------------------------------------------------------------------------
// Problem constants
// ----------------------------------------------------------------------------
#define IN_DIM   4096
#define OUT_DIM  4096
#define M_TOTAL  8192          // B*S = 4*2048

#define BM 128
#define BN 256
#define BK 64
#define STAGES 4
#define THREADS 512
#define K_ITERS (IN_DIM / BK)  // 64

// SMEM layout (relative to 1024-aligned base sb):
//   [0..31]   full barriers (4 x 8B)
//   [64..95]  empty barriers (4 x 8B)
//   [1024 + s*49152]          A tile stage s (128 x 64 halfs, SW128) 16KB
//   [1024 + s*49152 + 16384]  B tile stage s (256 x 64 halfs, SW128) 32KB
#define STAGE_BYTES 49152
#define SMEM_ALLOC  (1024 + STAGES * STAGE_BYTES + 1024)

// ----------------------------------------------------------------------------
// Scratch (device globals: allocation-free rule)
// ----------------------------------------------------------------------------
__device__ __half g_w16[(size_t)OUT_DIM * IN_DIM];   // 32MB
__device__ __half g_x16[(size_t)M_TOTAL * IN_DIM];   // 64MB

// ----------------------------------------------------------------------------
// PTX helpers (no tcgen05 — the toolchain targets sm_103 base)
// ----------------------------------------------------------------------------
__device__ __forceinline__ uint32_t smem_u32(const void* p) {
    uint32_t a;
    asm("{ .reg .u64 t; cvta.to.shared.u64 t, %1; cvt.u32.u64 %0, t; }"
        : "=r"(a) : "l"(p));
    return a;
}

#define MBARRIER_INIT(addr, cnt) \
    asm volatile("mbarrier.init.shared.b64 [%0], %1;" :: "r"(addr), "r"(cnt) : "memory")

#define MBARRIER_ARRIVE(addr) \
    asm volatile("mbarrier.arrive.shared.b64 _, [%0];" :: "r"(addr) : "memory")

#define MBARRIER_EXPECT_TX(addr, bytes) \
    asm volatile("mbarrier.arrive.expect_tx.shared.b64 _, [%0], %1;" \
                 :: "r"(addr), "r"(bytes) : "memory")

#define MBARRIER_WAIT_PARITY(addr, parity) do {                                   \
    uint32_t _m = (addr); uint32_t _p = (parity); uint32_t _done;                 \
    asm volatile("{\n\t.reg .pred p;\n\t"                                         \
        "mbarrier.try_wait.parity.acquire.cta.shared::cta.b64 p, [%1], %2;\n\t"   \
        "selp.b32 %0, 1, 0, p;\n\t}"                                              \
        : "=r"(_done) : "r"(_m), "r"(_p) : "memory");                             \
    if (!_done) {                                                                 \
        asm volatile("{\n\t.reg .pred P1;\n\t"                                    \
            "WL_%=:\n\t"                                                          \
            "mbarrier.try_wait.parity.acquire.cta.shared::cta.b64 P1, [%0], %1, 0x989680;\n\t" \
            "@P1 bra.uni WD_%=;\n\t"                                              \
            "bra.uni WL_%=;\n\t"                                                  \
            "WD_%=:\n\t}"                                                         \
            :: "r"(_m), "r"(_p) : "memory");                                      \
    }                                                                             \
} while (0)

#define TMA_LOAD_2D(dst, map_ptr, cx, cy, mbar)                                   \
    asm volatile(                                                                 \
        "cp.async.bulk.tensor.2d.shared::cta.global.tile.mbarrier::complete_tx::bytes " \
        "[%0], [%1, {%2, %3}], [%4];"                                             \
        :: "r"((uint32_t)(dst)), "l"(map_ptr), "r"((int)(cx)), "r"((int)(cy)),    \
           "r"((uint32_t)(mbar)) : "memory")

#define LDSM_X4(r0, r1, r2, r3, addr)                                             \
    asm volatile("ldmatrix.sync.aligned.m8n8.x4.shared.b16 {%0,%1,%2,%3}, [%4];"  \
        : "=r"(r0), "=r"(r1), "=r"(r2), "=r"(r3) : "r"(addr))

#define MMA16816(d, a, b0, b1)                                                    \
    asm volatile(                                                                 \
        "mma.sync.aligned.m16n8k16.row.col.f32.f16.f16.f32 "                      \
        "{%0,%1,%2,%3}, {%4,%5,%6,%7}, {%8,%9}, {%0,%1,%2,%3};"                   \
        : "+f"((d)[0]), "+f"((d)[1]), "+f"((d)[2]), "+f"((d)[3])                  \
        : "r"((a)[0]), "r"((a)[1]), "r"((a)[2]), "r"((a)[3]), "r"(b0), "r"(b1))

// ----------------------------------------------------------------------------
// Kernel 1: reconstruct fp16 weight from the three precision tiers.
// weight_high is zero outside the high mask and weight_medium is zero outside
// the medium mask (both masked at setup in the reference), so the masks are
// only needed to select the low tier: low <=> (wh==0 && wm==0). This avoids
// any dependence on how the harness encodes the bool mask inputs.
// weight_medium was float16 in the reference; the harness promotes it to
// float32 (rel_err=836 last round matched fp32-bits-read-as-halves garbage).
// ----------------------------------------------------------------------------
__global__ void __launch_bounds__(256) build_w16_kernel(
    const float4* __restrict__ wh, const float4* __restrict__ wmed,
    const int4* __restrict__ wl, const float* __restrict__ scale_p,
    uint2* __restrict__ w16)
{
    int i = blockIdx.x * blockDim.x + threadIdx.x;   // one per 4 elements
    float s = __ldg(scale_p);
    float4 h = wh[i];
    float4 m = wmed[i];
    int4  l = wl[i];

    float f0 = h.x + m.x + ((h.x == 0.0f && m.x == 0.0f) ? (float)l.x * s : 0.0f);
    float f1 = h.y + m.y + ((h.y == 0.0f && m.y == 0.0f) ? (float)l.y * s : 0.0f);
    float f2 = h.z + m.z + ((h.z == 0.0f && m.z == 0.0f) ? (float)l.z * s : 0.0f);
    float f3 = h.w + m.w + ((h.w == 0.0f && m.w == 0.0f) ? (float)l.w * s : 0.0f);

    __half2 o01 = __floats2half2_rn(f0, f1);
    __half2 o23 = __floats2half2_rn(f2, f3);
    uint2 o;
    o.x = *reinterpret_cast<uint32_t*>(&o01);
    o.y = *reinterpret_cast<uint32_t*>(&o23);
    w16[i] = o;
}

// ----------------------------------------------------------------------------
// Kernel 2: x fp32 -> fp16
// ----------------------------------------------------------------------------
__global__ void __launch_bounds__(256) convert_x_kernel(
    const float4* __restrict__ x, uint4* __restrict__ x16)
{
    int i = blockIdx.x * blockDim.x + threadIdx.x;   // one per 8 elements
    float4 a = x[2 * i], b = x[2 * i + 1];
    __half2 p0 = __floats2half2_rn(a.x, a.y);
    __half2 p1 = __floats2half2_rn(a.z, a.w);
    __half2 p2 = __floats2half2_rn(b.x, b.y);
    __half2 p3 = __floats2half2_rn(b.z, b.w);
    uint4 o;
    o.x = *reinterpret_cast<uint32_t*>(&p0);
    o.y = *reinterpret_cast<uint32_t*>(&p1);
    o.z = *reinterpret_cast<uint32_t*>(&p2);
    o.w = *reinterpret_cast<uint32_t*>(&p3);
    x16[i] = o;
}

// ----------------------------------------------------------------------------
// Kernel 3: HMMA fp16 GEMM (fp32 accum), 128x256 tile, TMA 4-stage pipeline.
//   D = X16[8192,4096] * W16[4096,4096]^T + bias  (fp32 out)
// 16 warps: 4 (M) x 4 (N); warp tile 32 x 64; mma.m16n8k16.
// ----------------------------------------------------------------------------
__global__ void __launch_bounds__(THREADS, 1) gemm_f16_kernel(
    const __grid_constant__ CUtensorMap tma_a,
    const __grid_constant__ CUtensorMap tma_b,
    const float* __restrict__ bias,
    float* __restrict__ out)
{
    extern __shared__ char smem_raw[];
    char* smem = (char*)(((uintptr_t)smem_raw + 1023) & ~(uintptr_t)1023);
    const uint32_t sb = smem_u32(smem);

    const int tid  = threadIdx.x;
    const int wid  = tid >> 5;
    const int lane = tid & 31;
    const int wm   = wid >> 2;   // 0..3 (M)
    const int wn   = wid & 3;    // 0..3 (N)

    const int n0 = blockIdx.x * BN;
    const int m0 = blockIdx.y * BM;

    const uint32_t FULL0  = sb;        // 4 x 8B
    const uint32_t EMPTY0 = sb + 64;   // 4 x 8B

    if (tid == 0) {
        #pragma unroll
        for (int s = 0; s < STAGES; ++s) {
            MBARRIER_INIT(FULL0 + s * 8, 1);
            MBARRIER_INIT(EMPTY0 + s * 8, 16);
        }
        asm volatile("fence.proxy.async.shared::cta;" ::: "memory");
    }
    __syncthreads();

    // Prologue: issue stages 0..STAGES-2
    if (tid == 0) {
        #pragma unroll
        for (int j = 0; j < STAGES - 1; ++j) {
            uint32_t st = sb + 1024 + j * STAGE_BYTES;
            MBARRIER_EXPECT_TX(FULL0 + j * 8, (uint32_t)STAGE_BYTES);
            TMA_LOAD_2D(st,         &tma_a, j * BK, m0, FULL0 + j * 8);
            TMA_LOAD_2D(st + 16384, &tma_b, j * BK, n0, FULL0 + j * 8);
        }
    }

    // Per-thread ldmatrix address components (SW128 swizzle on 128B rows)
    const uint32_t a_row = (uint32_t)(wm * 32 + (lane & 15));
    const uint32_t a_k0  = (uint32_t)((lane >> 4) << 4);            // bytes
    const uint32_t b_row = (uint32_t)(wn * 64 + (lane & 7) + ((lane >> 4) << 3));
    const uint32_t b_k0  = (uint32_t)(((lane >> 3) & 1) << 4);      // bytes
    const uint32_t swz   = (uint32_t)((lane & 7) << 4);             // same for A & B

    float c[2][8][4];
    #pragma unroll
    for (int t = 0; t < 2; ++t)
        #pragma unroll
        for (int n = 0; n < 8; ++n)
            #pragma unroll
            for (int k = 0; k < 4; ++k) c[t][n][k] = 0.0f;

    #pragma unroll 1
    for (int i = 0; i < K_ITERS; ++i) {
        const int s = i & (STAGES - 1);

        // Producer: issue stage i+STAGES-1
        if (tid == 0) {
            int j = i + STAGES - 1;
            if (j < K_ITERS) {
                int sj = j & (STAGES - 1);
                MBARRIER_WAIT_PARITY(EMPTY0 + sj * 8, ((j >> 2) + 1) & 1);
                uint32_t st = sb + 1024 + sj * STAGE_BYTES;
                MBARRIER_EXPECT_TX(FULL0 + sj * 8, (uint32_t)STAGE_BYTES);
                TMA_LOAD_2D(st,         &tma_a, j * BK, m0, FULL0 + sj * 8);
                TMA_LOAD_2D(st + 16384, &tma_b, j * BK, n0, FULL0 + sj * 8);
            }
        }

        MBARRIER_WAIT_PARITY(FULL0 + s * 8, (i >> 2) & 1);

        const uint32_t sA = sb + 1024 + s * STAGE_BYTES;
        const uint32_t sBt = sA + 16384;

        #pragma unroll
        for (int ks = 0; ks < 4; ++ks) {
            uint32_t a[2][4], b[4][4];
            const uint32_t kb = (uint32_t)(ks * 32);
            #pragma unroll
            for (int t = 0; t < 2; ++t) {
                uint32_t addr = sA + (a_row + t * 16) * 128 + ((kb + a_k0) ^ swz);
                LDSM_X4(a[t][0], a[t][1], a[t][2], a[t][3], addr);
            }
            #pragma unroll
            for (int g = 0; g < 4; ++g) {
                uint32_t addr = sBt + (b_row + g * 16) * 128 + ((kb + b_k0) ^ swz);
                LDSM_X4(b[g][0], b[g][1], b[g][2], b[g][3], addr);
            }
            #pragma unroll
            for (int t = 0; t < 2; ++t) {
                #pragma unroll
                for (int g = 0; g < 4; ++g) {
                    MMA16816(c[t][2 * g],     a[t], b[g][0], b[g][1]);
                    MMA16816(c[t][2 * g + 1], a[t], b[g][2], b[g][3]);
                }
            }
        }

        __syncwarp();
        if (lane == 0) MBARRIER_ARRIVE(EMPTY0 + s * 8);
    }

    // ---- Epilogue: registers -> gmem (float2 stores, bias added) ----
    const int m_base = m0 + wm * 32 + (lane >> 2);
    const int n_base = n0 + wn * 64 + (lane & 3) * 2;

    #pragma unroll
    for (int t = 0; t < 2; ++t) {
        #pragma unroll
        for (int nt = 0; nt < 8; ++nt) {
            const int col = n_base + nt * 8;
            const float2 bv = *reinterpret_cast<const float2*>(bias + col);
            const int r0 = m_base + t * 16;
            float2 v0, v1;
            v0.x = c[t][nt][0] + bv.x;
            v0.y = c[t][nt][1] + bv.y;
            v1.x = c[t][nt][2] + bv.x;
            v1.y = c[t][nt][3] + bv.y;
            *reinterpret_cast<float2*>(out + (size_t)r0 * OUT_DIM + col) = v0;
            *reinterpret_cast<float2*>(out + (size_t)(r0 + 8) * OUT_DIM + col) = v1;
        }
    }
}

// ----------------------------------------------------------------------------
// Host launcher
// ----------------------------------------------------------------------------
typedef CUresult (CUDAAPI *PFN_tmap_encode)(
    CUtensorMap*, CUtensorMapDataType, cuuint32_t, void*,
    const cuuint64_t*, const cuuint64_t*, const cuuint32_t*, const cuuint32_t*,
    CUtensorMapInterleave, CUtensorMapSwizzle, CUtensorMapL2promotion,
    CUtensorMapFloatOOBfill);

extern "C" void kernel_launch(void* const* d_in, const int* in_sizes, int n_in,
                              void* d_out, int out_size)
{
    const float*   x    = (const float*)d_in[0];
    const float*   wh   = (const float*)d_in[1];
    const float*   wmed = (const float*)d_in[2];   // fp16 promoted to fp32 by harness
    const int*     wl   = (const int*)d_in[3];
    const float*   ls   = (const float*)d_in[6];
    const float*   bias = (const float*)d_in[7];
    float* out = (float*)d_out;

    void* w16p = nullptr;
    void* x16p = nullptr;
    cudaGetSymbolAddress(&w16p, g_w16);
    cudaGetSymbolAddress(&x16p, g_x16);

    // Resolve cuTensorMapEncodeTiled through the runtime (no -lcuda needed).
    PFN_tmap_encode encode = nullptr;
    cudaDriverEntryPointQueryResult qres;
    cudaGetDriverEntryPointByVersion("cuTensorMapEncodeTiled", (void**)&encode,
                                     12000, cudaEnableDefault, &qres);

    CUtensorMap tma_a, tma_b;
    {
        cuuint64_t dims[2]    = { IN_DIM, M_TOTAL };
        cuuint64_t strides[1] = { IN_DIM * sizeof(__half) };
        cuuint32_t box[2]     = { BK, BM };           // 64 x 128
        cuuint32_t es[2]      = { 1, 1 };
        encode(&tma_a, CU_TENSOR_MAP_DATA_TYPE_FLOAT16, 2, x16p,
               dims, strides, box, es,
               CU_TENSOR_MAP_INTERLEAVE_NONE, CU_TENSOR_MAP_SWIZZLE_128B,
               CU_TENSOR_MAP_L2_PROMOTION_L2_128B, CU_TENSOR_MAP_FLOAT_OOB_FILL_NONE);
    }
    {
        cuuint64_t dims[2]    = { IN_DIM, OUT_DIM };
        cuuint64_t strides[1] = { IN_DIM * sizeof(__half) };
        cuuint32_t box[2]     = { BK, BN };           // 64 x 256
        cuuint32_t es[2]      = { 1, 1 };
        encode(&tma_b, CU_TENSOR_MAP_DATA_TYPE_FLOAT16, 2, w16p,
               dims, strides, box, es,
               CU_TENSOR_MAP_INTERLEAVE_NONE, CU_TENSOR_MAP_SWIZZLE_128B,
               CU_TENSOR_MAP_L2_PROMOTION_L2_128B, CU_TENSOR_MAP_FLOAT_OOB_FILL_NONE);
    }

    // Kernel 1: weight reconstruction (16.7M elems / 4 per thread)
    build_w16_kernel<<<(OUT_DIM * IN_DIM / 4) / 256, 256>>>(
        (const float4*)wh, (const float4*)wmed, (const int4*)wl, ls, (uint2*)w16p);

    // Kernel 2: x conversion (33.5M elems / 8 per thread)
    convert_x_kernel<<<((size_t)M_TOTAL * IN_DIM / 8) / 256, 256>>>(
        (const float4*)x, (uint4*)x16p);

    // Kernel 3: GEMM
    cudaFuncSetAttribute(gemm_f16_kernel,
                         cudaFuncAttributeMaxDynamicSharedMemorySize, SMEM_ALLOC);
    dim3 grid(OUT_DIM / BN, M_TOTAL / BM);   // (16, 64)
    gemm_f16_kernel<<<grid, THREADS, SMEM_ALLOC>>>(tma_a, tma_b, bias, out);
}

// round 4
// speedup vs baseline: 1.0006x; 1.0006x over previous
#include <cuda_runtime.h>
#include <cuda_fp16.h>
#include <cuda.h>
#include <cstdint>

// ----------------------------------------------------------------------------
// Problem constants
// ----------------------------------------------------------------------------
#define IN_DIM   4096
#define OUT_DIM  4096
#define M_TOTAL  8192          // B*S = 4*2048

#define BM 128
#define BN 256
#define BK 64
#define STAGES 4
#define THREADS 512
#define K_ITERS (IN_DIM / BK)  // 64

// SMEM layout (relative to 1024-aligned base sb):
//   [0..31]   full barriers (4 x 8B)
//   [64..95]  empty barriers (4 x 8B)
//   [1024 + s*49152]          A tile stage s (128 x 64 halfs, SW128) 16KB
//   [1024 + s*49152 + 16384]  B tile stage s (256 x 64 halfs, SW128) 32KB
#define STAGE_BYTES 49152
#define SMEM_ALLOC  (1024 + STAGES * STAGE_BYTES + 1024)

// ----------------------------------------------------------------------------
// Scratch (device globals: allocation-free rule)
// ----------------------------------------------------------------------------
__device__ __half g_w16[(size_t)OUT_DIM * IN_DIM];   // 32MB
__device__ __half g_x16[(size_t)M_TOTAL * IN_DIM];   // 64MB

// ----------------------------------------------------------------------------
// PTX helpers (no tcgen05 — the toolchain targets sm_103 base)
// ----------------------------------------------------------------------------
__device__ __forceinline__ uint32_t smem_u32(const void* p) {
    uint32_t a;
    asm("{ .reg .u64 t; cvta.to.shared.u64 t, %1; cvt.u32.u64 %0, t; }"
        : "=r"(a) : "l"(p));
    return a;
}

#define MBARRIER_INIT(addr, cnt) \
    asm volatile("mbarrier.init.shared.b64 [%0], %1;" :: "r"(addr), "r"(cnt) : "memory")

#define MBARRIER_ARRIVE(addr) \
    asm volatile("mbarrier.arrive.shared.b64 _, [%0];" :: "r"(addr) : "memory")

#define MBARRIER_EXPECT_TX(addr, bytes) \
    asm volatile("mbarrier.arrive.expect_tx.shared.b64 _, [%0], %1;" \
                 :: "r"(addr), "r"(bytes) : "memory")

#define MBARRIER_WAIT_PARITY(addr, parity) do {                                   \
    uint32_t _m = (addr); uint32_t _p = (parity); uint32_t _done;                 \
    asm volatile("{\n\t.reg .pred p;\n\t"                                         \
        "mbarrier.try_wait.parity.acquire.cta.shared::cta.b64 p, [%1], %2;\n\t"   \
        "selp.b32 %0, 1, 0, p;\n\t}"                                              \
        : "=r"(_done) : "r"(_m), "r"(_p) : "memory");                             \
    if (!_done) {                                                                 \
        asm volatile("{\n\t.reg .pred P1;\n\t"                                    \
            "WL_%=:\n\t"                                                          \
            "mbarrier.try_wait.parity.acquire.cta.shared::cta.b64 P1, [%0], %1, 0x989680;\n\t" \
            "@P1 bra.uni WD_%=;\n\t"                                              \
            "bra.uni WL_%=;\n\t"                                                  \
            "WD_%=:\n\t}"                                                         \
            :: "r"(_m), "r"(_p) : "memory");                                      \
    }                                                                             \
} while (0)

#define TMA_LOAD_2D(dst, map_ptr, cx, cy, mbar)                                   \
    asm volatile(                                                                 \
        "cp.async.bulk.tensor.2d.shared::cta.global.tile.mbarrier::complete_tx::bytes " \
        "[%0], [%1, {%2, %3}], [%4];"                                             \
        :: "r"((uint32_t)(dst)), "l"(map_ptr), "r"((int)(cx)), "r"((int)(cy)),    \
           "r"((uint32_t)(mbar)) : "memory")

#define LDSM_X4(r0, r1, r2, r3, addr)                                             \
    asm volatile("ldmatrix.sync.aligned.m8n8.x4.shared.b16 {%0,%1,%2,%3}, [%4];"  \
        : "=r"(r0), "=r"(r1), "=r"(r2), "=r"(r3) : "r"(addr))

#define MMA16816(d, a, b0, b1)                                                    \
    asm volatile(                                                                 \
        "mma.sync.aligned.m16n8k16.row.col.f32.f16.f16.f32 "                      \
        "{%0,%1,%2,%3}, {%4,%5,%6,%7}, {%8,%9}, {%0,%1,%2,%3};"                   \
        : "+f"((d)[0]), "+f"((d)[1]), "+f"((d)[2]), "+f"((d)[3])                  \
        : "r"((a)[0]), "r"((a)[1]), "r"((a)[2]), "r"((a)[3]), "r"(b0), "r"(b1))

// ----------------------------------------------------------------------------
// Kernel 1: fused prep. blockIdx.y == 0 -> weight reconstruction,
//           blockIdx.y == 1 -> x fp32 -> fp16 conversion.
// Both paths are DRAM-bound; fusing them into one launch removes a launch gap
// and keeps HBM saturated continuously.
// Low-tier selection uses (wh==0 && wm==0): weight_high / weight_medium are
// mask-zeroed at setup, so masks are redundant (avoids bool-dtype ambiguity).
// weight_medium arrives promoted to float32 by the harness.
// ----------------------------------------------------------------------------
__global__ void __launch_bounds__(256) prep_kernel(
    const float4* __restrict__ wh, const float4* __restrict__ wmed,
    const int4* __restrict__ wl, const float* __restrict__ scale_p,
    uint2* __restrict__ w16,
    const float4* __restrict__ x, uint4* __restrict__ x16)
{
    int i = blockIdx.x * blockDim.x + threadIdx.x;
    if (blockIdx.y == 0) {
        // ---- weight reconstruction: one thread per 4 elements ----
        float s = __ldg(scale_p);
        float4 h = wh[i];
        float4 m = wmed[i];
        int4  l = wl[i];

        float f0 = h.x + m.x + ((h.x == 0.0f && m.x == 0.0f) ? (float)l.x * s : 0.0f);
        float f1 = h.y + m.y + ((h.y == 0.0f && m.y == 0.0f) ? (float)l.y * s : 0.0f);
        float f2 = h.z + m.z + ((h.z == 0.0f && m.z == 0.0f) ? (float)l.z * s : 0.0f);
        float f3 = h.w + m.w + ((h.w == 0.0f && m.w == 0.0f) ? (float)l.w * s : 0.0f);

        __half2 o01 = __floats2half2_rn(f0, f1);
        __half2 o23 = __floats2half2_rn(f2, f3);
        uint2 o;
        o.x = *reinterpret_cast<uint32_t*>(&o01);
        o.y = *reinterpret_cast<uint32_t*>(&o23);
        w16[i] = o;
    } else {
        // ---- x conversion: one thread per 8 elements ----
        float4 a = x[2 * i], b = x[2 * i + 1];
        __half2 p0 = __floats2half2_rn(a.x, a.y);
        __half2 p1 = __floats2half2_rn(a.z, a.w);
        __half2 p2 = __floats2half2_rn(b.x, b.y);
        __half2 p3 = __floats2half2_rn(b.z, b.w);
        uint4 o;
        o.x = *reinterpret_cast<uint32_t*>(&p0);
        o.y = *reinterpret_cast<uint32_t*>(&p1);
        o.z = *reinterpret_cast<uint32_t*>(&p2);
        o.w = *reinterpret_cast<uint32_t*>(&p3);
        x16[i] = o;
    }
}

// ----------------------------------------------------------------------------
// Kernel 2: HMMA fp16 GEMM (fp32 accum), 128x256 tile, TMA 4-stage pipeline.
//   D = X16[8192,4096] * W16[4096,4096]^T + bias  (fp32 out)
// 16 warps: 4 (M) x 4 (N); warp tile 32 x 64; mma.m16n8k16.
// Stage is released (empty-arrive) right after the LAST ldmatrix of the
// iteration — the trailing MMA block runs on registers while TMA refills.
// ----------------------------------------------------------------------------
__global__ void __launch_bounds__(THREADS, 1) gemm_f16_kernel(
    const __grid_constant__ CUtensorMap tma_a,
    const __grid_constant__ CUtensorMap tma_b,
    const float* __restrict__ bias,
    float* __restrict__ out)
{
    extern __shared__ char smem_raw[];
    char* smem = (char*)(((uintptr_t)smem_raw + 1023) & ~(uintptr_t)1023);
    const uint32_t sb = smem_u32(smem);

    const int tid  = threadIdx.x;
    const int wid  = tid >> 5;
    const int lane = tid & 31;
    const int wm   = wid >> 2;   // 0..3 (M)
    const int wn   = wid & 3;    // 0..3 (N)

    const int n0 = blockIdx.x * BN;
    const int m0 = blockIdx.y * BM;

    const uint32_t FULL0  = sb;        // 4 x 8B
    const uint32_t EMPTY0 = sb + 64;   // 4 x 8B

    if (tid == 0) {
        #pragma unroll
        for (int s = 0; s < STAGES; ++s) {
            MBARRIER_INIT(FULL0 + s * 8, 1);
            MBARRIER_INIT(EMPTY0 + s * 8, 16);
        }
        asm volatile("fence.proxy.async.shared::cta;" ::: "memory");
    }
    __syncthreads();

    // Prologue: issue stages 0..STAGES-2
    if (tid == 0) {
        #pragma unroll
        for (int j = 0; j < STAGES - 1; ++j) {
            uint32_t st = sb + 1024 + j * STAGE_BYTES;
            MBARRIER_EXPECT_TX(FULL0 + j * 8, (uint32_t)STAGE_BYTES);
            TMA_LOAD_2D(st,         &tma_a, j * BK, m0, FULL0 + j * 8);
            TMA_LOAD_2D(st + 16384, &tma_b, j * BK, n0, FULL0 + j * 8);
        }
    }

    // Per-thread ldmatrix address components (SW128 swizzle on 128B rows)
    const uint32_t a_row = (uint32_t)(wm * 32 + (lane & 15));
    const uint32_t a_k0  = (uint32_t)((lane >> 4) << 4);            // bytes
    const uint32_t b_row = (uint32_t)(wn * 64 + (lane & 7) + ((lane >> 4) << 3));
    const uint32_t b_k0  = (uint32_t)(((lane >> 3) & 1) << 4);      // bytes
    const uint32_t swz   = (uint32_t)((lane & 7) << 4);             // same for A & B

    float c[2][8][4];
    #pragma unroll
    for (int t = 0; t < 2; ++t)
        #pragma unroll
        for (int n = 0; n < 8; ++n)
            #pragma unroll
            for (int k = 0; k < 4; ++k) c[t][n][k] = 0.0f;

    #pragma unroll 1
    for (int i = 0; i < K_ITERS; ++i) {
        const int s = i & (STAGES - 1);

        // Producer: issue stage i+STAGES-1
        if (tid == 0) {
            int j = i + STAGES - 1;
            if (j < K_ITERS) {
                int sj = j & (STAGES - 1);
                MBARRIER_WAIT_PARITY(EMPTY0 + sj * 8, ((j >> 2) + 1) & 1);
                uint32_t st = sb + 1024 + sj * STAGE_BYTES;
                MBARRIER_EXPECT_TX(FULL0 + sj * 8, (uint32_t)STAGE_BYTES);
                TMA_LOAD_2D(st,         &tma_a, j * BK, m0, FULL0 + sj * 8);
                TMA_LOAD_2D(st + 16384, &tma_b, j * BK, n0, FULL0 + sj * 8);
            }
        }

        MBARRIER_WAIT_PARITY(FULL0 + s * 8, (i >> 2) & 1);

        const uint32_t sA = sb + 1024 + s * STAGE_BYTES;
        const uint32_t sBt = sA + 16384;

        #pragma unroll
        for (int ks = 0; ks < 4; ++ks) {
            uint32_t a[2][4], b[4][4];
            const uint32_t kb = (uint32_t)(ks * 32);
            #pragma unroll
            for (int t = 0; t < 2; ++t) {
                uint32_t addr = sA + (a_row + t * 16) * 128 + ((kb + a_k0) ^ swz);
                LDSM_X4(a[t][0], a[t][1], a[t][2], a[t][3], addr);
            }
            #pragma unroll
            for (int g = 0; g < 4; ++g) {
                uint32_t addr = sBt + (b_row + g * 16) * 128 + ((kb + b_k0) ^ swz);
                LDSM_X4(b[g][0], b[g][1], b[g][2], b[g][3], addr);
            }
            if (ks == 3) {
                // All smem reads for this stage are issued; release it now so
                // TMA refills while the final MMA block runs on registers.
                __syncwarp();
                if (lane == 0) MBARRIER_ARRIVE(EMPTY0 + s * 8);
            }
            #pragma unroll
            for (int t = 0; t < 2; ++t) {
                #pragma unroll
                for (int g = 0; g < 4; ++g) {
                    MMA16816(c[t][2 * g],     a[t], b[g][0], b[g][1]);
                    MMA16816(c[t][2 * g + 1], a[t], b[g][2], b[g][3]);
                }
            }
        }
    }

    // ---- Epilogue: registers -> gmem (float2 stores, bias added) ----
    const int m_base = m0 + wm * 32 + (lane >> 2);
    const int n_base = n0 + wn * 64 + (lane & 3) * 2;

    #pragma unroll
    for (int t = 0; t < 2; ++t) {
        #pragma unroll
        for (int nt = 0; nt < 8; ++nt) {
            const int col = n_base + nt * 8;
            const float2 bv = *reinterpret_cast<const float2*>(bias + col);
            const int r0 = m_base + t * 16;
            float2 v0, v1;
            v0.x = c[t][nt][0] + bv.x;
            v0.y = c[t][nt][1] + bv.y;
            v1.x = c[t][nt][2] + bv.x;
            v1.y = c[t][nt][3] + bv.y;
            *reinterpret_cast<float2*>(out + (size_t)r0 * OUT_DIM + col) = v0;
            *reinterpret_cast<float2*>(out + (size_t)(r0 + 8) * OUT_DIM + col) = v1;
        }
    }
}

// ----------------------------------------------------------------------------
// Host launcher
// ----------------------------------------------------------------------------
typedef CUresult (CUDAAPI *PFN_tmap_encode)(
    CUtensorMap*, CUtensorMapDataType, cuuint32_t, void*,
    const cuuint64_t*, const cuuint64_t*, const cuuint32_t*, const cuuint32_t*,
    CUtensorMapInterleave, CUtensorMapSwizzle, CUtensorMapL2promotion,
    CUtensorMapFloatOOBfill);

extern "C" void kernel_launch(void* const* d_in, const int* in_sizes, int n_in,
                              void* d_out, int out_size)
{
    const float*   x    = (const float*)d_in[0];
    const float*   wh   = (const float*)d_in[1];
    const float*   wmed = (const float*)d_in[2];   // fp16 promoted to fp32 by harness
    const int*     wl   = (const int*)d_in[3];
    const float*   ls   = (const float*)d_in[6];
    const float*   bias = (const float*)d_in[7];
    float* out = (float*)d_out;

    void* w16p = nullptr;
    void* x16p = nullptr;
    cudaGetSymbolAddress(&w16p, g_w16);
    cudaGetSymbolAddress(&x16p, g_x16);

    // Resolve cuTensorMapEncodeTiled through the runtime (no -lcuda needed).
    PFN_tmap_encode encode = nullptr;
    cudaDriverEntryPointQueryResult qres;
    cudaGetDriverEntryPointByVersion("cuTensorMapEncodeTiled", (void**)&encode,
                                     12000, cudaEnableDefault, &qres);

    CUtensorMap tma_a, tma_b;
    {
        cuuint64_t dims[2]    = { IN_DIM, M_TOTAL };
        cuuint64_t strides[1] = { IN_DIM * sizeof(__half) };
        cuuint32_t box[2]     = { BK, BM };           // 64 x 128
        cuuint32_t es[2]      = { 1, 1 };
        encode(&tma_a, CU_TENSOR_MAP_DATA_TYPE_FLOAT16, 2, x16p,
               dims, strides, box, es,
               CU_TENSOR_MAP_INTERLEAVE_NONE, CU_TENSOR_MAP_SWIZZLE_128B,
               CU_TENSOR_MAP_L2_PROMOTION_L2_128B, CU_TENSOR_MAP_FLOAT_OOB_FILL_NONE);
    }
    {
        cuuint64_t dims[2]    = { IN_DIM, OUT_DIM };
        cuuint64_t strides[1] = { IN_DIM * sizeof(__half) };
        cuuint32_t box[2]     = { BK, BN };           // 64 x 256
        cuuint32_t es[2]      = { 1, 1 };
        encode(&tma_b, CU_TENSOR_MAP_DATA_TYPE_FLOAT16, 2, w16p,
               dims, strides, box, es,
               CU_TENSOR_MAP_INTERLEAVE_NONE, CU_TENSOR_MAP_SWIZZLE_128B,
               CU_TENSOR_MAP_L2_PROMOTION_L2_128B, CU_TENSOR_MAP_FLOAT_OOB_FILL_NONE);
    }

    // Kernel 1: fused weight reconstruction + x conversion.
    // y=0: 16.7M weight elems / 4 per thread; y=1: 33.5M x elems / 8 per thread.
    dim3 pgrid((OUT_DIM * IN_DIM / 4) / 256, 2);
    prep_kernel<<<pgrid, 256>>>(
        (const float4*)wh, (const float4*)wmed, (const int4*)wl, ls,
        (uint2*)w16p, (const float4*)x, (uint4*)x16p);

    // Kernel 2: GEMM
    cudaFuncSetAttribute(gemm_f16_kernel,
                         cudaFuncAttributeMaxDynamicSharedMemorySize, SMEM_ALLOC);
    dim3 grid(OUT_DIM / BN, M_TOTAL / BM);   // (16, 64)
    gemm_f16_kernel<<<grid, THREADS, SMEM_ALLOC>>>(tma_a, tma_b, bias, out);
}